// round 13
// baseline (speedup 1.0000x reference)
#include <cuda_runtime.h>
#include <cstdint>

// Problem constants (fixed by the reference)
#define N_VOX   65536      // 2*32*32*32 = 256*256 exactly
#define DD      512        // emb dim
#define EE      64         // heads
#define VV      16         // outputs per head
#define NB      256        // blocks in count/scatter grids
#define GB      296        // gemm grid = two blocks per SM (one wave, occ=2)
#define CHUNK   222        // ceil(N_VOX / GB): sorted positions per gemm block

// Scratch (allocation-free rule: __device__ globals)
__device__ int g_partial[NB * EE];    // per-block head histograms
__device__ int g_blockbase[NB * EE];  // exclusive prefix over blocks, per head
__device__ int g_runbase[EE];         // exclusive prefix over heads (global)
__device__ int g_perm[N_VOX];
__device__ int g_headSorted[N_VOX];

// ---------------------------------------------------------------------------
// 1) per-block histogram (no global atomics, no pre-zero kernel)
__global__ void k_count(const int* __restrict__ bt, const int* __restrict__ b2h) {
    __shared__ int hist[EE];
    int t = threadIdx.x;
    if (t < EE) hist[t] = 0;
    __syncthreads();
    int i = blockIdx.x * 256 + t;
    int h = __ldg(&b2h[__ldg(&bt[i])]);
    atomicAdd(&hist[h], 1);
    __syncthreads();
    if (t < EE) g_partial[blockIdx.x * EE + t] = hist[t];
}

// 2) scan: per-head prefix over blocks + exclusive scan over head totals
//    unroll 32 -> 32 L2 loads in flight per batch (8 batches instead of 32)
__global__ void k_scan() {
    int h = threadIdx.x;          // 64 threads
    int s = 0;
    #pragma unroll 32
    for (int b = 0; b < NB; b++) {            // coalesced: addr = b*64 + h
        int c = g_partial[b * EE + h];
        g_blockbase[b * EE + h] = s;
        s += c;
    }
    __shared__ int tot[EE];
    tot[h] = s;
    __syncthreads();
    if (h == 0) {
        int a = 0;
        #pragma unroll
        for (int j = 0; j < EE; j++) { int c = tot[j]; tot[j] = a; a += c; }
    }
    __syncthreads();
    g_runbase[h] = tot[h];
}

// 3) scatter into head-sorted order (shared atomics only)
__global__ void k_scatter(const int* __restrict__ bt, const int* __restrict__ b2h) {
    __shared__ int sbase[EE];
    __shared__ int scnt[EE];
    int t = threadIdx.x;
    if (t < EE) {
        sbase[t] = g_runbase[t] + g_blockbase[blockIdx.x * EE + t];
        scnt[t] = 0;
    }
    __syncthreads();
    int i = blockIdx.x * 256 + t;
    int h = __ldg(&b2h[__ldg(&bt[i])]);
    int r = atomicAdd(&scnt[h], 1);
    int pos = sbase[h] + r;
    g_perm[pos] = i;
    g_headSorted[pos] = h;
}

// ---------------------------------------------------------------------------
// 4) gather-GEMM, 296 blocks = 2 per SM (one wave, occ=2 for latency hiding):
//    - each block consumes CHUNK=222 sorted positions in ONE pass
//    - 4 lanes per voxel row -> 64B-coalesced x loads (few L1tex wavefronts)
//    - compute split into two STRICTLY SEQUENTIAL 2-voxel sub-batches
//      (#pragma unroll 1) so at most acc[2][16]=64 accumulator regs are live
//      -> fits the 128-reg occ=2 budget with margin; NO spills
//    - W tile of the current head in shared; packed dual-FMA fma.rn.f32x2
//    - 2-step shfl_xor butterfly finishes each dot product

#define FMA2(acc, a, b) asm("fma.rn.f32x2 %0, %1, %2, %0;" : "+l"(acc) : "l"(a), "l"(b))

__global__ __launch_bounds__(256, 2) void k_gemm(
    const float* __restrict__ x,
    const float* __restrict__ Wh,
    const float* __restrict__ bh,
    float* __restrict__ out)
{
    __shared__ float sW[VV * DD];   // 32 KB: one head's weights
    __shared__ float sB[VV];
    __shared__ int   sMin;

    int t    = threadIdx.x;
    int s    = t & 3;               // sublane within group of 4
    int gb   = t >> 2;              // group index in block (0..63)
    int lane = t & 31;
    unsigned gm = 0xFu << (lane & ~3u);   // shfl mask: this lane's group

    int start = blockIdx.x * CHUNK;
    int end   = min(start + CHUNK, N_VOX);

    // single pass: CHUNK (222) <= 256 positions per block
    int vox[4], hd[4];
    unsigned pend = 0;
    #pragma unroll
    for (int k = 0; k < 4; k++) {
        int p = start + gb * 4 + k;
        if (p < end) {
            vox[k] = g_perm[p];
            hd[k]  = g_headSorted[p];
            pend |= (1u << k);
        } else {
            vox[k] = 0; hd[k] = 0x7fffffff;
        }
    }

    if (t == 0) sMin = 0x7fffffff;
    __syncthreads();   // sMin init visible before first atomicMin

    for (;;) {
        int mymin = 0x7fffffff;
        #pragma unroll
        for (int k = 0; k < 4; k++)
            if (pend & (1u << k)) mymin = min(mymin, hd[k]);
        if (mymin != 0x7fffffff) atomicMin(&sMin, mymin);
        __syncthreads();
        int cur = sMin;
        __syncthreads();                 // everyone has read sMin
        if (t == 0) sMin = 0x7fffffff;   // reset for next round
        if (cur == 0x7fffffff) break;    // uniform exit (block done)

        // cooperative load of W[cur] (8192 floats) + bias
        {
            const float4* wg = (const float4*)(Wh + (size_t)cur * VV * DD);
            float4* ws = (float4*)sW;
            #pragma unroll
            for (int j = 0; j < 8; j++) ws[t + j * 256] = __ldg(&wg[t + j * 256]);
            if (t < VV) sB[t] = __ldg(&bh[cur * VV + t]);
        }
        __syncthreads();

        // which of this group's 4 voxels belong to the current run?
        unsigned act = 0;
        #pragma unroll
        for (int k = 0; k < 4; k++)
            if ((pend & (1u << k)) && hd[k] == cur) act |= (1u << k);

        // two 2-voxel sub-batches, forced sequential (unroll 1) so only
        // acc[2][16] (64 regs) is ever live -> no spill at occ=2
        #pragma unroll 1
        for (int half = 0; half < 2; half++) {
            unsigned a2 = (act >> (half * 2)) & 3u;
            if (!a2) continue;                    // group-uniform
            int k0 = half * 2, k1 = half * 2 + 1;

            const ulonglong2* xp0 = (const ulonglong2*)(x + (size_t)vox[k0] * DD);
            const ulonglong2* xp1 = (const ulonglong2*)(x + (size_t)vox[k1] * DD);

            unsigned long long acc[2][VV];
            #pragma unroll
            for (int v = 0; v < VV; v++) { acc[0][v] = 0ull; acc[1][v] = 0ull; }

            // lane s owns chunks c = s, s+4, ..., s+124 (32 x 16B);
            // group reads 64B consecutive per iteration (1 line per row).
            #pragma unroll 2
            for (int i = 0; i < 32; i++) {
                int c = i * 4 + s;
                ulonglong2 xv0, xv1;
                if (a2 & 1u) xv0 = __ldg(&xp0[c]); else { xv0.x = 0; xv0.y = 0; }
                if (a2 & 2u) xv1 = __ldg(&xp1[c]); else { xv1.x = 0; xv1.y = 0; }
                #pragma unroll
                for (int v = 0; v < VV; v++) {
                    ulonglong2 wv = *(const ulonglong2*)&sW[v * DD + c * 4];
                    FMA2(acc[0][v], xv0.x, wv.x);
                    FMA2(acc[0][v], xv0.y, wv.y);
                    FMA2(acc[1][v], xv1.x, wv.x);
                    FMA2(acc[1][v], xv1.y, wv.y);
                }
            }

            // collapse f32x2 packs, butterfly-reduce across 4 lanes, store
            #pragma unroll
            for (int j = 0; j < 2; j++) {
                int k = half * 2 + j;
                if (!(a2 & (1u << j))) continue;  // group-uniform
                float res[VV];
                #pragma unroll
                for (int v = 0; v < VV; v++) {
                    float lo = __uint_as_float((unsigned)(acc[j][v] & 0xffffffffull));
                    float hi = __uint_as_float((unsigned)(acc[j][v] >> 32));
                    res[v] = lo + hi;
                }
                #pragma unroll
                for (int v = 0; v < VV; v++) {
                    res[v] += __shfl_xor_sync(gm, res[v], 1);
                    res[v] += __shfl_xor_sync(gm, res[v], 2);
                }
                int vb = s * 4;                   // lane s stores [4s,4s+4)
                float4 o;
                o.x = res[vb + 0] + sB[vb + 0];
                o.y = res[vb + 1] + sB[vb + 1];
                o.z = res[vb + 2] + sB[vb + 2];
                o.w = res[vb + 3] + sB[vb + 3];
                *(float4*)(out + (size_t)vox[k] * VV + vb) = o;
            }
        }
        pend &= ~act;
        __syncthreads();             // protect sW until all consumers finish
    }
}

// ---------------------------------------------------------------------------
extern "C" void kernel_launch(void* const* d_in, const int* in_sizes, int n_in,
                              void* d_out, int out_size)
{
    const int*   bt  = (const int*)  d_in[0];   // block_type_grid (int32, N)
    const float* x   = (const float*)d_in[1];   // x (f32, N x 512)
    const float* Wh  = (const float*)d_in[2];   // W_heads (f32, 64 x 16 x 512)
    const float* bh  = (const float*)d_in[3];   // b_heads (f32, 64 x 16)
    const int*   b2h = (const int*)  d_in[4];   // block2head (int32, 256)
    float* out = (float*)d_out;

    k_count<<<NB, 256>>>(bt, b2h);
    k_scan<<<1, EE>>>();
    k_scatter<<<NB, 256>>>(bt, b2h);
    k_gemm<<<GB, 256>>>(x, Wh, bh, out);
}

// round 14
// speedup vs baseline: 1.0305x; 1.0305x over previous
#include <cuda_runtime.h>
#include <cstdint>

// Problem constants (fixed by the reference)
#define N_VOX   65536      // 2*32*32*32 = 256*256 exactly
#define DD      512        // emb dim
#define EE      64         // heads
#define VV      16         // outputs per head
#define NB      256        // blocks in count/scatter grids
#define GB      296        // gemm grid = two blocks per SM (one wave, occ=2)
#define CHUNK   222        // ceil(N_VOX / GB): sorted positions per gemm block

// Scratch (allocation-free rule: __device__ globals)
__device__ int g_partial[NB * EE];    // per-block head histograms
__device__ int g_blockbase[NB * EE];  // exclusive prefix over blocks, per head
__device__ int g_runbase[EE];         // exclusive prefix over heads (global)
__device__ int g_perm[N_VOX];
__device__ int g_headSorted[N_VOX];

// ---------------------------------------------------------------------------
// 1) per-block histogram (no global atomics, no pre-zero kernel)
__global__ void k_count(const int* __restrict__ bt, const int* __restrict__ b2h) {
    __shared__ int hist[EE];
    int t = threadIdx.x;
    if (t < EE) hist[t] = 0;
    __syncthreads();
    int i = blockIdx.x * 256 + t;
    int h = __ldg(&b2h[__ldg(&bt[i])]);
    atomicAdd(&hist[h], 1);
    __syncthreads();
    if (t < EE) g_partial[blockIdx.x * EE + t] = hist[t];
}

// 2) scan: per-head prefix over blocks + exclusive scan over head totals
__global__ void k_scan() {
    int h = threadIdx.x;          // 64 threads
    int s = 0;
    #pragma unroll 32
    for (int b = 0; b < NB; b++) {            // coalesced: addr = b*64 + h
        int c = g_partial[b * EE + h];
        g_blockbase[b * EE + h] = s;
        s += c;
    }
    __shared__ int tot[EE];
    tot[h] = s;
    __syncthreads();
    if (h == 0) {
        int a = 0;
        #pragma unroll
        for (int j = 0; j < EE; j++) { int c = tot[j]; tot[j] = a; a += c; }
    }
    __syncthreads();
    g_runbase[h] = tot[h];
}

// 3) scatter into head-sorted order (shared atomics only)
__global__ void k_scatter(const int* __restrict__ bt, const int* __restrict__ b2h) {
    __shared__ int sbase[EE];
    __shared__ int scnt[EE];
    int t = threadIdx.x;
    if (t < EE) {
        sbase[t] = g_runbase[t] + g_blockbase[blockIdx.x * EE + t];
        scnt[t] = 0;
    }
    __syncthreads();
    int i = blockIdx.x * 256 + t;
    int h = __ldg(&b2h[__ldg(&bt[i])]);
    int r = atomicAdd(&scnt[h], 1);
    int pos = sbase[h] + r;
    g_perm[pos] = i;
    g_headSorted[pos] = h;
}

// ---------------------------------------------------------------------------
// 4) gather-GEMM. R13 change (from measurement): inner loop batches 8
//    independent LDG.128 (4 i-iterations x 2 voxels) BEFORE the FMA block
//    -> ~8KB/SM in flight (was 4KB, measured DRAM only 1.8TB/s, latency-bound
//    at issue=25%). Everything else unchanged from the passing R11 kernel.

#define FMA2(acc, a, b) asm("fma.rn.f32x2 %0, %1, %2, %0;" : "+l"(acc) : "l"(a), "l"(b))

__global__ __launch_bounds__(256, 2) void k_gemm(
    const float* __restrict__ x,
    const float* __restrict__ Wh,
    const float* __restrict__ bh,
    float* __restrict__ out)
{
    __shared__ float sW[VV * DD];   // 32 KB: one head's weights
    __shared__ float sB[VV];
    __shared__ int   sMin;

    int t    = threadIdx.x;
    int s    = t & 3;               // sublane within group of 4
    int gb   = t >> 2;              // group index in block (0..63)
    int lane = t & 31;
    unsigned gm = 0xFu << (lane & ~3u);   // shfl mask: this lane's group

    int start = blockIdx.x * CHUNK;
    int end   = min(start + CHUNK, N_VOX);

    // single pass: CHUNK (222) <= 256 positions per block
    int vox[4], hd[4];
    unsigned pend = 0;
    #pragma unroll
    for (int k = 0; k < 4; k++) {
        int p = start + gb * 4 + k;
        if (p < end) {
            vox[k] = g_perm[p];
            hd[k]  = g_headSorted[p];
            pend |= (1u << k);
        } else {
            vox[k] = 0; hd[k] = 0x7fffffff;
        }
    }

    if (t == 0) sMin = 0x7fffffff;
    __syncthreads();   // sMin init visible before first atomicMin

    for (;;) {
        int mymin = 0x7fffffff;
        #pragma unroll
        for (int k = 0; k < 4; k++)
            if (pend & (1u << k)) mymin = min(mymin, hd[k]);
        if (mymin != 0x7fffffff) atomicMin(&sMin, mymin);
        __syncthreads();
        int cur = sMin;
        __syncthreads();                 // everyone has read sMin
        if (t == 0) sMin = 0x7fffffff;   // reset for next round
        if (cur == 0x7fffffff) break;    // uniform exit (block done)

        // cooperative load of W[cur] (8192 floats) + bias
        {
            const float4* wg = (const float4*)(Wh + (size_t)cur * VV * DD);
            float4* ws = (float4*)sW;
            #pragma unroll
            for (int j = 0; j < 8; j++) ws[t + j * 256] = __ldg(&wg[t + j * 256]);
            if (t < VV) sB[t] = __ldg(&bh[cur * VV + t]);
        }
        __syncthreads();

        // which of this group's 4 voxels belong to the current run?
        unsigned act = 0;
        #pragma unroll
        for (int k = 0; k < 4; k++)
            if ((pend & (1u << k)) && hd[k] == cur) act |= (1u << k);

        // two 2-voxel sub-batches, forced sequential (unroll 1) so only
        // acc[2][16] (64 regs) is ever live -> no spill at occ=2
        #pragma unroll 1
        for (int half = 0; half < 2; half++) {
            unsigned a2 = (act >> (half * 2)) & 3u;
            if (!a2) continue;                    // group-uniform
            int k0 = half * 2, k1 = half * 2 + 1;

            const ulonglong2* xp0 = (const ulonglong2*)(x + (size_t)vox[k0] * DD);
            const ulonglong2* xp1 = (const ulonglong2*)(x + (size_t)vox[k1] * DD);

            unsigned long long acc[2][VV];
            #pragma unroll
            for (int v = 0; v < VV; v++) { acc[0][v] = 0ull; acc[1][v] = 0ull; }

            // lane s owns chunks c = s, s+4, ..., s+124 (32 x 16B);
            // group reads 64B consecutive per iteration (1 line per row).
            // Batch 8 independent LDGs (4 iters x 2 voxels) before the FMAs.
            #pragma unroll 1
            for (int i = 0; i < 32; i += 4) {
                ulonglong2 xv0[4], xv1[4];
                #pragma unroll
                for (int u = 0; u < 4; u++) {
                    int c = (i + u) * 4 + s;
                    if (a2 & 1u) xv0[u] = __ldg(&xp0[c]);
                    else { xv0[u].x = 0ull; xv0[u].y = 0ull; }
                    if (a2 & 2u) xv1[u] = __ldg(&xp1[c]);
                    else { xv1[u].x = 0ull; xv1[u].y = 0ull; }
                }
                #pragma unroll
                for (int u = 0; u < 4; u++) {
                    int c = (i + u) * 4 + s;
                    #pragma unroll
                    for (int v = 0; v < VV; v++) {
                        ulonglong2 wv = *(const ulonglong2*)&sW[v * DD + c * 4];
                        FMA2(acc[0][v], xv0[u].x, wv.x);
                        FMA2(acc[0][v], xv0[u].y, wv.y);
                        FMA2(acc[1][v], xv1[u].x, wv.x);
                        FMA2(acc[1][v], xv1[u].y, wv.y);
                    }
                }
            }

            // collapse f32x2 packs, butterfly-reduce across 4 lanes, store
            #pragma unroll
            for (int j = 0; j < 2; j++) {
                int k = half * 2 + j;
                if (!(a2 & (1u << j))) continue;  // group-uniform
                float res[VV];
                #pragma unroll
                for (int v = 0; v < VV; v++) {
                    float lo = __uint_as_float((unsigned)(acc[j][v] & 0xffffffffull));
                    float hi = __uint_as_float((unsigned)(acc[j][v] >> 32));
                    res[v] = lo + hi;
                }
                #pragma unroll
                for (int v = 0; v < VV; v++) {
                    res[v] += __shfl_xor_sync(gm, res[v], 1);
                    res[v] += __shfl_xor_sync(gm, res[v], 2);
                }
                int vb = s * 4;                   // lane s stores [4s,4s+4)
                float4 o;
                o.x = res[vb + 0] + sB[vb + 0];
                o.y = res[vb + 1] + sB[vb + 1];
                o.z = res[vb + 2] + sB[vb + 2];
                o.w = res[vb + 3] + sB[vb + 3];
                *(float4*)(out + (size_t)vox[k] * VV + vb) = o;
            }
        }
        pend &= ~act;
        __syncthreads();             // protect sW until all consumers finish
    }
}

// ---------------------------------------------------------------------------
extern "C" void kernel_launch(void* const* d_in, const int* in_sizes, int n_in,
                              void* d_out, int out_size)
{
    const int*   bt  = (const int*)  d_in[0];   // block_type_grid (int32, N)
    const float* x   = (const float*)d_in[1];   // x (f32, N x 512)
    const float* Wh  = (const float*)d_in[2];   // W_heads (f32, 64 x 16 x 512)
    const float* bh  = (const float*)d_in[3];   // b_heads (f32, 64 x 16)
    const int*   b2h = (const int*)  d_in[4];   // block2head (int32, 256)
    float* out = (float*)d_out;

    k_count<<<NB, 256>>>(bt, b2h);
    k_scan<<<1, EE>>>();
    k_scatter<<<NB, 256>>>(bt, b2h);
    k_gemm<<<GB, 256>>>(x, Wh, bh, out);
}